// round 1
// baseline (speedup 1.0000x reference)
#include <cuda_runtime.h>

#define NMAX 64
#define OUTD 224
#define HW   50176          // 224*224
#define FC   2048
#define FHW  49             // 7*7

// global scratch (no allocations allowed)
__device__ int  d_cnt[NMAX * HW];
__device__ int4 d_box[NMAX];

// ---------------- union-find in shared memory ----------------
__device__ __forceinline__ int uf_find(int* P, int i) {
    int p = P[i];
    while (p != i) {
        int gp = P[p];
        if (gp != p) P[i] = gp;   // path halving (benign race)
        i = p; p = gp;
    }
    return i;
}

__device__ __forceinline__ void uf_union(int* P, int a, int b) {
    int ra = uf_find(P, a), rb = uf_find(P, b);
    while (ra != rb) {
        if (ra < rb) { int t = ra; ra = rb; rb = t; }
        int old = atomicCAS(&P[ra], ra, rb);   // link larger root under smaller
        if (old == ra) break;
        ra = uf_find(P, old);
        rb = uf_find(P, rb);
    }
}

// ---------------- kernel 1: heat + upsample + CCL + bbox (one CTA per image) ----------------
__global__ __launch_bounds__(1024, 1) void k_heat_ccl(
    const float* __restrict__ feat,
    float* __restrict__ outHeat,
    float* __restrict__ outCoords)
{
    extern __shared__ int P[];                 // HW ints = 196 KB (parent array)
    __shared__ float sPart[20 * FHW];
    __shared__ float sH[FHW];
    __shared__ int   sX0[OUTD], sX1[OUTD];
    __shared__ float sWt[OUTD];
    __shared__ float sMn, sMx;
    __shared__ int   sBC[32], sBR[32];
    __shared__ int   sBest, sRmin, sRmax, sCmin, sCmax;

    const int n   = blockIdx.x;
    const int tid = threadIdx.x;
    const float* f = feat + (size_t)n * (FC * FHW);

    // Phase A: heat[p] = max_c |feat[c,p]|  (coalesced: addr = tid + 980*k)
    if (tid < 20 * FHW) {
        int p = tid % FHW, cg = tid / FHW;
        float m = 0.f;
        for (int c = cg; c < FC; c += 20)
            m = fmaxf(m, fabsf(f[c * FHW + p]));
        sPart[tid] = m;
    }
    // interpolation tables (independent work) — exact reference arithmetic:
    // g = i/223 (IEEE div), xs = g*6, x0 = clip(floor), wx = xs - x0
    for (int i = tid; i < OUTD; i += 1024) {
        float g  = (float)i / 223.0f;
        float xs = __fmul_rn(g, 6.0f);
        int x0 = (int)floorf(xs);
        x0 = min(max(x0, 0), 6);
        sX0[i] = x0;
        sX1[i] = min(x0 + 1, 6);
        sWt[i] = __fsub_rn(xs, (float)x0);
    }
    if (tid == 0) { sRmin = HW; sRmax = -1; sCmin = HW; sCmax = -1; }
    __syncthreads();

    if (tid < FHW) {
        float mm = sPart[tid];
        #pragma unroll
        for (int j = 1; j < 20; j++) mm = fmaxf(mm, sPart[j * FHW + tid]);
        sH[tid] = mm;
    }
    __syncthreads();
    if (tid == 0) {
        float mn = sH[0], mx = sH[0];
        for (int j = 1; j < FHW; j++) { mn = fminf(mn, sH[j]); mx = fmaxf(mx, sH[j]); }
        sMn = mn; sMx = mx;
    }
    __syncthreads();
    if (tid < FHW) sH[tid] = (sH[tid] - sMn) / (sMx - sMn);   // matches (f-mn)/(mx-mn)
    __syncthreads();

    // Phase C: bilinear upsample 7->224, write out_heatmap, build mask, zero counts
    float* oh  = outHeat + (size_t)n * HW;
    int*   cnt = d_cnt   + (size_t)n * HW;
    for (int o = tid; o < HW; o += 1024) {
        int r = o / OUTD, c = o % OUTD;
        int x0 = sX0[r], x1 = sX1[r]; float wx = sWt[r];
        int y0 = sX0[c], y1 = sX1[c]; float wy = sWt[c];
        float v00 = sH[x0 * 7 + y0], v01 = sH[x0 * 7 + y1];
        float v10 = sH[x1 * 7 + y0], v11 = sH[x1 * 7 + y1];
        float iwy = __fsub_rn(1.f, wy);
        float a = __fadd_rn(__fmul_rn(iwy, v00), __fmul_rn(wy, v01));
        float b = __fadd_rn(__fmul_rn(iwy, v10), __fmul_rn(wy, v11));
        float v = __fadd_rn(__fmul_rn(__fsub_rn(1.f, wx), a), __fmul_rn(wx, b));
        oh[o] = v;
        P[o]  = (v > 0.7f) ? o : -1;
        cnt[o] = 0;
    }
    __syncthreads();

    // Phase D: 8-connected union (E, S, SE, SW edges cover all adjacencies)
    for (int o = tid; o < HW; o += 1024) {
        if (P[o] < 0) continue;
        int r = o / OUTD, c = o % OUTD;
        if (c + 1 < OUTD && P[o + 1] >= 0) uf_union(P, o, o + 1);
        if (r + 1 < OUTD) {
            if (P[o + OUTD] >= 0)                    uf_union(P, o, o + OUTD);
            if (c + 1 < OUTD && P[o + OUTD + 1] >= 0) uf_union(P, o, o + OUTD + 1);
            if (c > 0       && P[o + OUTD - 1] >= 0) uf_union(P, o, o + OUTD - 1);
        }
    }
    __syncthreads();

    // Phase E: flatten roots + warp-aggregated counting (HW % 1024 == 0 -> uniform trips)
    for (int o = tid; o < HW; o += 1024) {
        int root = -1;
        if (P[o] >= 0) { root = uf_find(P, o); P[o] = root; }
        unsigned act = __ballot_sync(0xffffffffu, root >= 0);
        if (root >= 0) {
            unsigned peers = __match_any_sync(act, root);
            int leader = __ffs(peers) - 1;
            if ((tid & 31) == leader)
                atomicAdd(&cnt[root], __popc(peers));
        }
    }
    __syncthreads();

    // Phase F: argmax count, tie -> smallest root (matches jnp.argmax first-occurrence)
    int bc = 0, br = 0x7fffffff;
    for (int o = tid; o < HW; o += 1024) {
        int cc = __ldcg(&cnt[o]);
        if (cc > bc || (cc == bc && o < br)) { bc = cc; br = o; }
    }
    #pragma unroll
    for (int off = 16; off; off >>= 1) {
        int oc  = __shfl_down_sync(0xffffffffu, bc, off);
        int orr = __shfl_down_sync(0xffffffffu, br, off);
        if (oc > bc || (oc == bc && orr < br)) { bc = oc; br = orr; }
    }
    if ((tid & 31) == 0) { sBC[tid >> 5] = bc; sBR[tid >> 5] = br; }
    __syncthreads();
    if (tid < 32) {
        bc = sBC[tid]; br = sBR[tid];
        #pragma unroll
        for (int off = 16; off; off >>= 1) {
            int oc  = __shfl_down_sync(0xffffffffu, bc, off);
            int orr = __shfl_down_sync(0xffffffffu, br, off);
            if (oc > bc || (oc == bc && orr < br)) { bc = oc; br = orr; }
        }
        if (tid == 0) sBest = br;
    }
    __syncthreads();

    // Phase G: bbox of largest component
    int best = sBest;
    int rmin = HW, rmax = -1, cmin = HW, cmax = -1;
    for (int o = tid; o < HW; o += 1024) {
        if (P[o] == best) {
            int r = o / OUTD, c = o % OUTD;
            rmin = min(rmin, r); rmax = max(rmax, r);
            cmin = min(cmin, c); cmax = max(cmax, c);
        }
    }
    if (rmax >= 0) {
        atomicMin(&sRmin, rmin); atomicMax(&sRmax, rmax);
        atomicMin(&sCmin, cmin); atomicMax(&sCmax, cmax);
    }
    __syncthreads();
    if (tid == 0) {
        int xmin = sRmin, xmax = sRmax, ymin = sCmin, ymax = sCmax;
        if (xmax < 0) { xmin = 0; ymin = 0; xmax = OUTD - 1; ymax = OUTD - 1; } // empty fallback
        d_box[n] = make_int4(xmin, xmax, ymin, ymax);
        float* co = outCoords + n * 4;
        co[0] = (float)ymin; co[1] = (float)xmin;   // torch coord order [ymin,xmin,ymax,xmax]
        co[2] = (float)ymax; co[3] = (float)xmax;
    }
}

// ---------------- kernel 2: crop + align-corners bilinear resize ----------------
__global__ void k_crop(const float* __restrict__ x, float* __restrict__ out, int total)
{
    int idx = blockIdx.x * blockDim.x + threadIdx.x;
    if (idx >= total) return;
    int c  = idx % OUTD;
    int r  = (idx / OUTD) % OUTD;
    int nc = idx / HW;          // n*3 + ch
    int n  = nc / 3;

    int4 bx = d_box[n];         // xmin, xmax, ymin, ymax (rows=x, cols=y)
    int Lx = max(bx.y - bx.x, 1);
    int Ly = max(bx.w - bx.z, 1);
    float xs = __fadd_rn((float)bx.x, __fmul_rn((float)r / 223.0f, (float)(Lx - 1)));
    float ys = __fadd_rn((float)bx.z, __fmul_rn((float)c / 223.0f, (float)(Ly - 1)));

    int x0 = min(max((int)floorf(xs), 0), 223), x1 = min(x0 + 1, 223);
    int y0 = min(max((int)floorf(ys), 0), 223), y1 = min(y0 + 1, 223);
    float wx = __fsub_rn(xs, (float)x0), wy = __fsub_rn(ys, (float)y0);

    const float* img = x + (size_t)nc * HW;
    float v00 = __ldg(&img[x0 * OUTD + y0]);
    float v01 = __ldg(&img[x0 * OUTD + y1]);
    float v10 = __ldg(&img[x1 * OUTD + y0]);
    float v11 = __ldg(&img[x1 * OUTD + y1]);

    float iwy = __fsub_rn(1.f, wy);
    float a = __fadd_rn(__fmul_rn(iwy, v00), __fmul_rn(wy, v01));
    float b = __fadd_rn(__fmul_rn(iwy, v10), __fmul_rn(wy, v11));
    out[idx] = __fadd_rn(__fmul_rn(__fsub_rn(1.f, wx), a), __fmul_rn(wx, b));
}

// ---------------- launch ----------------
extern "C" void kernel_launch(void* const* d_in, const int* in_sizes, int n_in,
                              void* d_out, int out_size)
{
    const float* x    = (const float*)d_in[0];   // (N,3,224,224)
    const float* feat = (const float*)d_in[1];   // (N,2048,7,7)
    float* out = (float*)d_out;

    int N = in_sizes[0] / (3 * HW);
    if (N > NMAX) N = NMAX;

    float* outCrop   = out;
    float* outHeat   = out + (size_t)N * 3 * HW;
    float* outCoords = out + (size_t)N * 3 * HW + (size_t)N * HW;

    cudaFuncSetAttribute(k_heat_ccl, cudaFuncAttributeMaxDynamicSharedMemorySize, HW * 4);

    k_heat_ccl<<<N, 1024, HW * 4>>>(feat, outHeat, outCoords);

    int total = N * 3 * HW;
    k_crop<<<(total + 255) / 256, 256>>>(x, outCrop, total);
}

// round 2
// speedup vs baseline: 2.4444x; 2.4444x over previous
#include <cuda_runtime.h>

#define NMAX 64
#define OUTD 224
#define HW   50176          // 224*224
#define FC   2048
#define FHW  49             // 7*7
#define RMAX 112            // hard max runs per row (alternating bits)
#define NRUNS (OUTD * RMAX) // 25088

// global scratch (no allocations allowed)
__device__ int d_cnt[NMAX * NRUNS];
__device__ int4 d_box[NMAX];
__device__ __align__(16) float2 d_tr[NMAX * OUTD];   // per-(n,row): (x0 as int bits, wx)
__device__ __align__(16) float2 d_tc[NMAX * OUTD];   // per-(n,col): (y0 as int bits, wy)

// ---------------- union-find over run ids in shared memory ----------------
__device__ __forceinline__ int uf_find(int* P, int i) {
    int p = P[i];
    while (p != i) {
        int gp = P[p];
        if (gp != p) P[i] = gp;   // path halving (benign race)
        i = p; p = gp;
    }
    return i;
}

__device__ __forceinline__ void uf_union(int* P, int a, int b) {
    int ra = uf_find(P, a), rb = uf_find(P, b);
    while (ra != rb) {
        if (ra < rb) { int t = ra; ra = rb; rb = t; }
        int old = atomicCAS(&P[ra], ra, rb);   // link larger root under smaller
        if (old == ra) break;
        ra = uf_find(P, old);
        rb = uf_find(P, rb);
    }
}

// ---------------- kernel 1: heat + upsample + run-based CCL + bbox + tables ----------------
__global__ __launch_bounds__(1024, 1) void k_heat_ccl(
    const float* __restrict__ feat,
    float* __restrict__ outHeat,
    float* __restrict__ outCoords)
{
    extern __shared__ int S[];          // [NRUNS] packed run (start<<16|end), [NRUNS] parent
    int* sSE = S;
    int* P   = S + NRUNS;

    __shared__ float sPart[20 * FHW];
    __shared__ float sH[FHW];
    __shared__ int   sX0[OUTD], sX1[OUTD];
    __shared__ float sWt[OUTD];
    __shared__ unsigned sMask[OUTD * 7];   // 224 bits per row
    __shared__ int   sRunCnt[OUTD];
    __shared__ float sMn, sMx;
    __shared__ int   sBC[32], sBR[32];
    __shared__ int   sBest, sBestCnt, sRmin, sRmax, sCmin, sCmax;
    __shared__ int4  sBox;

    const int n   = blockIdx.x;
    const int tid = threadIdx.x;
    const float* f = feat + (size_t)n * (FC * FHW);

    // Phase A: heat[p] = max_c |feat[c,p]| (coalesced: addr = tid + 980*k) + misc init
    if (tid < 20 * FHW) {
        int p = tid % FHW, cg = tid / FHW;
        float m = 0.f;
        #pragma unroll 4
        for (int c = cg; c < FC; c += 20)
            m = fmaxf(m, fabsf(f[c * FHW + p]));
        sPart[tid] = m;
    }
    // interpolation tables for 7->224 upsample (exact reference arithmetic)
    for (int i = tid; i < OUTD; i += 1024) {
        float g  = (float)i / 223.0f;
        float xs = __fmul_rn(g, 6.0f);
        int x0 = (int)floorf(xs);
        x0 = min(max(x0, 0), 6);
        sX0[i] = x0;
        sX1[i] = min(x0 + 1, 6);
        sWt[i] = __fsub_rn(xs, (float)x0);
    }
    for (int g = tid; g < NRUNS; g += 1024) P[g] = g;   // parent init
    if (tid == 0) { sRmin = HW; sRmax = -1; sCmin = HW; sCmax = -1; }
    __syncthreads();

    // Phase B: finish max reduce, normalize
    if (tid < FHW) {
        float mm = sPart[tid];
        #pragma unroll
        for (int j = 1; j < 20; j++) mm = fmaxf(mm, sPart[j * FHW + tid]);
        sH[tid] = mm;
    }
    __syncthreads();
    if (tid == 0) {
        float mn = sH[0], mx = sH[0];
        for (int j = 1; j < FHW; j++) { mn = fminf(mn, sH[j]); mx = fmaxf(mx, sH[j]); }
        sMn = mn; sMx = mx;
    }
    __syncthreads();
    if (tid < FHW) sH[tid] = (sH[tid] - sMn) / (sMx - sMn);
    __syncthreads();

    // Phase C: bilinear upsample 7->224, write out_heatmap, build bitmask via ballot
    float* oh = outHeat + (size_t)n * HW;
    for (int o = tid; o < HW; o += 1024) {         // 49 uniform iterations, full warps
        int r = o / OUTD, c = o % OUTD;
        int x0 = sX0[r], x1 = sX1[r]; float wx = sWt[r];
        int y0 = sX0[c], y1 = sX1[c]; float wy = sWt[c];
        float v00 = sH[x0 * 7 + y0], v01 = sH[x0 * 7 + y1];
        float v10 = sH[x1 * 7 + y0], v11 = sH[x1 * 7 + y1];
        float iwy = __fsub_rn(1.f, wy);
        float a = __fadd_rn(__fmul_rn(iwy, v00), __fmul_rn(wy, v01));
        float b = __fadd_rn(__fmul_rn(iwy, v10), __fmul_rn(wy, v11));
        float v = __fadd_rn(__fmul_rn(__fsub_rn(1.f, wx), a), __fmul_rn(wx, b));
        oh[o] = v;
        unsigned m = __ballot_sync(0xffffffffu, v > 0.7f);   // lane l <-> bit l <-> col bit
        if ((tid & 31) == 0) sMask[o >> 5] = m;              // 224 % 32 == 0: no straddle
    }
    __syncthreads();

    // Phase D: per-row run extraction (thread r handles row r) + zero used cnt slots
    if (tid < OUTD) {
        int r = tid, base = r * 7, cntR = 0, pos = 0;
        int* cnt = d_cnt + (size_t)n * NRUNS + r * RMAX;
        while (pos < 224) {
            int w = pos >> 5;
            unsigned m = sMask[base + w] & (0xffffffffu << (pos & 31));
            while (m == 0 && ++w < 7) m = sMask[base + w];
            if (m == 0) break;
            int start = (w << 5) + __ffs(m) - 1;
            unsigned inv = (~sMask[base + w]) & (0xffffffffu << (start & 31));
            int w2 = w;
            while (inv == 0 && ++w2 < 7) inv = ~sMask[base + w2];
            int end = (w2 == 7) ? 223 : ((w2 << 5) + __ffs(inv) - 2);
            sSE[r * RMAX + cntR] = (start << 16) | end;
            cnt[cntR] = 0;
            cntR++;
            pos = end + 2;
        }
        sRunCnt[r] = cntR;
    }
    __syncthreads();

    // Phase E: union overlapping runs between adjacent rows (8-connectivity)
    if (tid < OUTD - 1) {
        int r = tid;
        int ca = sRunCnt[r], cb = sRunCnt[r + 1];
        int i = 0, j = 0;
        while (i < ca && j < cb) {
            int A = sSE[r * RMAX + i];        int a0 = A >> 16, a1 = A & 0xffff;
            int B = sSE[(r + 1) * RMAX + j];  int b0 = B >> 16, b1 = B & 0xffff;
            if (b0 <= a1 + 1 && a0 <= b1 + 1)
                uf_union(P, r * RMAX + i, (r + 1) * RMAX + j);
            if (a1 <= b1) i++; else j++;
        }
    }
    __syncthreads();

    // Phase F: count pixels per component (add run length at root)
    {
        int* cnt = d_cnt + (size_t)n * NRUNS;
        for (int g = tid; g < NRUNS; g += 1024) {
            int row = g / RMAX, slot = g - row * RMAX;
            if (slot < sRunCnt[row]) {
                int A = sSE[g];
                int len = (A & 0xffff) - (A >> 16) + 1;
                atomicAdd(&cnt[uf_find(P, g)], len);
            }
        }
    }
    __syncthreads();

    // Phase G: argmax (count, tie -> smallest root id == smallest min-pixel-label)
    {
        const int* cnt = d_cnt + (size_t)n * NRUNS;
        int bc = 0, br = 0x7fffffff;
        for (int g = tid; g < NRUNS; g += 1024) {
            int row = g / RMAX, slot = g - row * RMAX;
            if (slot < sRunCnt[row]) {
                int cc = __ldcg(&cnt[g]);     // bypass L1: atomics landed in L2
                if (cc > bc || (cc == bc && g < br)) { bc = cc; br = g; }
            }
        }
        #pragma unroll
        for (int off = 16; off; off >>= 1) {
            int oc  = __shfl_down_sync(0xffffffffu, bc, off);
            int orr = __shfl_down_sync(0xffffffffu, br, off);
            if (oc > bc || (oc == bc && orr < br)) { bc = oc; br = orr; }
        }
        if ((tid & 31) == 0) { sBC[tid >> 5] = bc; sBR[tid >> 5] = br; }
        __syncthreads();
        if (tid < 32) {
            bc = sBC[tid]; br = sBR[tid];
            #pragma unroll
            for (int off = 16; off; off >>= 1) {
                int oc  = __shfl_down_sync(0xffffffffu, bc, off);
                int orr = __shfl_down_sync(0xffffffffu, br, off);
                if (oc > bc || (oc == bc && orr < br)) { bc = oc; br = orr; }
            }
            if (tid == 0) { sBest = br; sBestCnt = bc; }
        }
    }
    __syncthreads();

    // Phase H: bbox of largest component (iterate runs)
    {
        int best = sBest;
        if (sBestCnt > 0) {
            int rmin = HW, rmax = -1, cmin = HW, cmax = -1;
            for (int g = tid; g < NRUNS; g += 1024) {
                int row = g / RMAX, slot = g - row * RMAX;
                if (slot < sRunCnt[row] && uf_find(P, g) == best) {
                    int A = sSE[g];
                    rmin = min(rmin, row); rmax = max(rmax, row);
                    cmin = min(cmin, A >> 16); cmax = max(cmax, A & 0xffff);
                }
            }
            if (rmax >= 0) {
                atomicMin(&sRmin, rmin); atomicMax(&sRmax, rmax);
                atomicMin(&sCmin, cmin); atomicMax(&sCmax, cmax);
            }
        }
    }
    __syncthreads();

    if (tid == 0) {
        int xmin = sRmin, xmax = sRmax, ymin = sCmin, ymax = sCmax;
        if (sBestCnt <= 0 || xmax < 0) { xmin = 0; ymin = 0; xmax = OUTD - 1; ymax = OUTD - 1; }
        sBox = make_int4(xmin, xmax, ymin, ymax);
        d_box[n] = sBox;
        float* co = outCoords + n * 4;
        co[0] = (float)ymin; co[1] = (float)xmin;    // torch order [ymin,xmin,ymax,xmax]
        co[2] = (float)ymax; co[3] = (float)xmax;
    }
    __syncthreads();

    // Phase I: precompute crop interpolation tables for kernel 2
    {
        int4 bx = sBox;
        if (tid < OUTD) {                       // row table: src x in [xmin, xmax)
            int r = tid;
            int Lx = max(bx.y - bx.x, 1);
            float g  = (float)r / 223.0f;
            float xs = __fadd_rn((float)bx.x, __fmul_rn(g, (float)(Lx - 1)));
            int x0 = min(max((int)floorf(xs), 0), 223);
            d_tr[n * OUTD + r] = make_float2(__int_as_float(x0), __fsub_rn(xs, (float)x0));
        } else if (tid >= 256 && tid < 256 + OUTD) {   // col table: src y in [ymin, ymax)
            int c = tid - 256;
            int Ly = max(bx.w - bx.z, 1);
            float g  = (float)c / 223.0f;
            float ys = __fadd_rn((float)bx.z, __fmul_rn(g, (float)(Ly - 1)));
            int y0 = min(max((int)floorf(ys), 0), 223);
            d_tc[n * OUTD + c] = make_float2(__int_as_float(y0), __fsub_rn(ys, (float)y0));
        }
    }
}

// ---------------- kernel 2: crop + align-corners bilinear resize (4 outputs/thread) ----------------
__device__ __forceinline__ float bilin1(const float* __restrict__ r0,
                                        const float* __restrict__ r1,
                                        float y0f, float wy, float wx)
{
    int y0 = __float_as_int(y0f);
    int y1 = min(y0 + 1, 223);
    float v00 = __ldg(&r0[y0]), v01 = __ldg(&r0[y1]);
    float v10 = __ldg(&r1[y0]), v11 = __ldg(&r1[y1]);
    float iwy = __fsub_rn(1.f, wy);
    float a = __fadd_rn(__fmul_rn(iwy, v00), __fmul_rn(wy, v01));
    float b = __fadd_rn(__fmul_rn(iwy, v10), __fmul_rn(wy, v11));
    return __fadd_rn(__fmul_rn(__fsub_rn(1.f, wx), a), __fmul_rn(wx, b));
}

__global__ void k_crop(const float* __restrict__ x, float* __restrict__ out, int total4)
{
    int idx = blockIdx.x * blockDim.x + threadIdx.x;
    if (idx >= total4) return;
    int c4 = idx % 56;                 // 4-col group
    int r  = (idx / 56) % OUTD;
    int nc = idx / (56 * OUTD);        // n*3 + ch
    int n  = nc / 3;
    int c0 = c4 * 4;

    float2 tr = d_tr[n * OUTD + r];
    int x0 = __float_as_int(tr.x);
    int x1 = min(x0 + 1, 223);
    float wx = tr.y;

    const float* img  = x + (size_t)nc * HW;
    const float* row0 = img + x0 * OUTD;
    const float* row1 = img + x1 * OUTD;

    // 4 consecutive col-table entries = 32 aligned bytes
    const float4* tc4 = reinterpret_cast<const float4*>(d_tc + n * OUTD + c0);
    float4 ta = tc4[0];   // (y0f_a, wy_a, y0f_b, wy_b)
    float4 tb = tc4[1];   // (y0f_c, wy_c, y0f_d, wy_d)

    float4 res;
    res.x = bilin1(row0, row1, ta.x, ta.y, wx);
    res.y = bilin1(row0, row1, ta.z, ta.w, wx);
    res.z = bilin1(row0, row1, tb.x, tb.y, wx);
    res.w = bilin1(row0, row1, tb.z, tb.w, wx);

    *reinterpret_cast<float4*>(out + (size_t)nc * HW + r * OUTD + c0) = res;
}

// ---------------- launch ----------------
extern "C" void kernel_launch(void* const* d_in, const int* in_sizes, int n_in,
                              void* d_out, int out_size)
{
    const float* x    = (const float*)d_in[0];   // (N,3,224,224)
    const float* feat = (const float*)d_in[1];   // (N,2048,7,7)
    float* out = (float*)d_out;

    int N = in_sizes[0] / (3 * HW);
    if (N > NMAX) N = NMAX;

    float* outCrop   = out;
    float* outHeat   = out + (size_t)N * 3 * HW;
    float* outCoords = out + (size_t)N * 3 * HW + (size_t)N * HW;

    static int smemSet = 0;
    if (!smemSet) {
        cudaFuncSetAttribute(k_heat_ccl, cudaFuncAttributeMaxDynamicSharedMemorySize,
                             2 * NRUNS * (int)sizeof(int));
        smemSet = 1;
    }

    k_heat_ccl<<<N, 1024, 2 * NRUNS * sizeof(int)>>>(feat, outHeat, outCoords);

    int total4 = N * 3 * OUTD * 56;
    k_crop<<<(total4 + 255) / 256, 256>>>(x, outCrop, total4);
}